// round 1
// baseline (speedup 1.0000x reference)
#include <cuda_runtime.h>
#include <cstdint>

// ---------------------------------------------------------------------------
// Problem constants
// ---------------------------------------------------------------------------
#define BATCH 16
#define CDIM  768
#define SDIM  4096          // H*W = 64*64
#define KCOND 1024

// LN kernel tiling
#define PIX     32          // pixels per block
#define THREADS 256

// ---------------------------------------------------------------------------
// Scratch (no allocations allowed -> device globals)
// ---------------------------------------------------------------------------
__device__ float g_tmp0[BATCH * CDIM];
__device__ float g_tmp1[BATCH * CDIM];

// ---------------------------------------------------------------------------
// Small GEMM: out[b,n] = bias[n] + sum_k X[b,k] * W[n,k]
// B=16 fixed. One warp per output column n. 8 warps/block.
// ---------------------------------------------------------------------------
__global__ void __launch_bounds__(256) gemm16(
    const float* __restrict__ X, const float* __restrict__ W,
    const float* __restrict__ bias, float* __restrict__ out, int K, int N)
{
    int warp = threadIdx.x >> 5;
    int lane = threadIdx.x & 31;
    int n = blockIdx.x * 8 + warp;
    if (n >= N) return;

    const float* wrow = W + (size_t)n * K;
    float acc[BATCH];
#pragma unroll
    for (int b = 0; b < BATCH; b++) acc[b] = 0.f;

    for (int k = lane; k < K; k += 32) {
        float wv = __ldg(wrow + k);
#pragma unroll
        for (int b = 0; b < BATCH; b++)
            acc[b] += wv * __ldg(X + b * K + k);
    }
#pragma unroll
    for (int b = 0; b < BATCH; b++) {
#pragma unroll
        for (int off = 16; off; off >>= 1)
            acc[b] += __shfl_xor_sync(0xffffffffu, acc[b], off);
    }
    if (lane < BATCH)
        out[lane * N + n] = acc[lane] + __ldg(bias + n);
}

// ---------------------------------------------------------------------------
// Fused broadcast-add + LayerNorm(C) + transpose-free store.
//   in : spatial [B, C, S]  (S contiguous)
//   proj[B, C] broadcast over S
//   out: y[B, C, S]  where LN is over C for each (b, s)
//
// One block = 32 consecutive s-values for one batch, full C staged in SMEM.
// spatial is read exactly once from DRAM.
// ---------------------------------------------------------------------------
__global__ void __launch_bounds__(THREADS) fused_add_ln(
    const float* __restrict__ spatial,
    const float* __restrict__ proj,
    const float* __restrict__ gamma,
    const float* __restrict__ beta,
    float* __restrict__ out)
{
    extern __shared__ float smem[];
    float* tile    = smem;                    // CDIM * PIX
    float* proj_s  = tile   + CDIM * PIX;     // CDIM
    float* gamma_s = proj_s + CDIM;           // CDIM
    float* beta_s  = gamma_s + CDIM;          // CDIM
    float* psum    = beta_s + CDIM;           // 8 * PIX
    float* psq     = psum   + 8 * PIX;        // 8 * PIX
    float* mean_s  = psq    + 8 * PIX;        // PIX
    float* rstd_s  = mean_s + PIX;            // PIX

    const int b  = blockIdx.x >> 7;           // / (SDIM/PIX = 128)
    const int s0 = (blockIdx.x & 127) * PIX;
    const int tid = threadIdx.x;

    // per-block constants into smem
    for (int i = tid; i < CDIM; i += THREADS) {
        proj_s[i]  = proj[b * CDIM + i];
        gamma_s[i] = gamma[i];
        beta_s[i]  = beta[i];
    }
    __syncthreads();

    const size_t gbase = (size_t)b * CDIM * SDIM + s0;
    const int p4 = tid & 7;        // which float4 within the 32-pixel row
    const int c0 = tid >> 3;       // c row, stepped by 32

    // ---- load + broadcast add: one DRAM read of the tile ----
#pragma unroll
    for (int it = 0; it < CDIM / 32; it++) {
        int c = c0 + it * 32;
        float4 v = *(const float4*)(spatial + gbase + (size_t)c * SDIM + p4 * 4);
        float pj = proj_s[c];
        v.x += pj; v.y += pj; v.z += pj; v.w += pj;
        *(float4*)(tile + c * PIX + p4 * 4) = v;
    }
    __syncthreads();

    // ---- stats: 8 threads per pixel, conflict-free (bank = p) ----
    {
        const int p   = tid & 31;
        const int sub = tid >> 5;          // 0..7
        float s = 0.f, sq = 0.f;
        const int cbeg = sub * (CDIM / 8);
#pragma unroll 8
        for (int c = cbeg; c < cbeg + CDIM / 8; c++) {
            float x = tile[c * PIX + p];
            s  += x;
            sq += x * x;
        }
        psum[sub * PIX + p] = s;
        psq [sub * PIX + p] = sq;
    }
    __syncthreads();

    if (tid < PIX) {
        float s = 0.f, sq = 0.f;
#pragma unroll
        for (int i = 0; i < 8; i++) { s += psum[i * PIX + tid]; sq += psq[i * PIX + tid]; }
        const float inv = 1.0f / CDIM;
        float mu  = s * inv;
        float var = sq * inv - mu * mu;
        mean_s[tid] = mu;
        rstd_s[tid] = rsqrtf(var + 1e-5f);
    }
    __syncthreads();

    // ---- normalize + store ----
    const float4 mu4 = *(const float4*)(mean_s + p4 * 4);
    const float4 rs4 = *(const float4*)(rstd_s + p4 * 4);
#pragma unroll
    for (int it = 0; it < CDIM / 32; it++) {
        int c = c0 + it * 32;
        float4 v = *(const float4*)(tile + c * PIX + p4 * 4);
        float g  = gamma_s[c];
        float bt = beta_s[c];
        v.x = (v.x - mu4.x) * rs4.x * g + bt;
        v.y = (v.y - mu4.y) * rs4.y * g + bt;
        v.z = (v.z - mu4.z) * rs4.z * g + bt;
        v.w = (v.w - mu4.w) * rs4.w * g + bt;
        *(float4*)(out + gbase + (size_t)c * SDIM + p4 * 4) = v;
    }
}

// ---------------------------------------------------------------------------
// Launcher
// ---------------------------------------------------------------------------
extern "C" void kernel_launch(void* const* d_in, const int* in_sizes, int n_in,
                              void* d_out, int out_size)
{
    const float* spatial     = (const float*)d_in[0];
    const float* conditioning= (const float*)d_in[1];
    const float* w_cond      = (const float*)d_in[2];
    const float* b_cond      = (const float*)d_in[3];
    const float* in_proj_w   = (const float*)d_in[4];
    const float* in_proj_b   = (const float*)d_in[5];
    const float* attn_out_w  = (const float*)d_in[6];
    const float* attn_out_b  = (const float*)d_in[7];
    const float* w_out       = (const float*)d_in[8];
    const float* b_out       = (const float*)d_in[9];
    const float* ln_gamma    = (const float*)d_in[10];
    const float* ln_beta     = (const float*)d_in[11];
    float* out = (float*)d_out;

    float *tmp0, *tmp1;
    cudaGetSymbolAddress((void**)&tmp0, g_tmp0);
    cudaGetSymbolAddress((void**)&tmp1, g_tmp1);

    const int smem_bytes = (CDIM * PIX + 3 * CDIM + 16 * PIX + 2 * PIX) * sizeof(float);
    static bool attr_set = false;   // idempotent attribute, not a work guard
    cudaFuncSetAttribute(fused_add_ln, cudaFuncAttributeMaxDynamicSharedMemorySize, smem_bytes);
    (void)attr_set;

    dim3 gblk(CDIM / 8);

    // cond = conditioning @ w_cond^T + b_cond
    gemm16<<<gblk, 256>>>(conditioning, w_cond, b_cond, tmp0, KCOND, CDIM);
    // v = cond @ wv^T + bv   (wv = in_proj_w rows [2C, 3C))
    gemm16<<<gblk, 256>>>(tmp0, in_proj_w + 2 * CDIM * CDIM, in_proj_b + 2 * CDIM,
                          tmp1, CDIM, CDIM);
    // attn = v @ attn_out_w^T + attn_out_b
    gemm16<<<gblk, 256>>>(tmp1, attn_out_w, attn_out_b, tmp0, CDIM, CDIM);
    // proj = attn @ w_out^T + b_out
    gemm16<<<gblk, 256>>>(tmp0, w_out, b_out, tmp1, CDIM, CDIM);

    // fused add + layernorm
    fused_add_ln<<<BATCH * (SDIM / PIX), THREADS, smem_bytes>>>(
        spatial, tmp1, ln_gamma, ln_beta, out);
}

// round 2
// speedup vs baseline: 3.1320x; 3.1320x over previous
#include <cuda_runtime.h>
#include <cstdint>

// ---------------------------------------------------------------------------
// Problem constants
// ---------------------------------------------------------------------------
#define BATCH 16
#define CDIM  768
#define SDIM  4096          // H*W = 64*64
#define KCOND 1024

// LN kernel tiling
#define PIX     32          // pixels per block
#define THREADS 256

// ---------------------------------------------------------------------------
// Scratch (no allocations allowed -> device globals)
// ---------------------------------------------------------------------------
__device__ float g_tmp0[BATCH * CDIM];
__device__ float g_tmp1[BATCH * CDIM];

// ---------------------------------------------------------------------------
// Small GEMM: out[b,n] = bias[n] + sum_k X[b,k] * W[n,k]
// One BLOCK per output column n (grid = N = 768 -> full chip coverage).
// 256 threads split K with float4 loads; two-stage reduction.
// ---------------------------------------------------------------------------
__global__ void __launch_bounds__(256) gemm16_col(
    const float* __restrict__ X, const float* __restrict__ W,
    const float* __restrict__ bias, float* __restrict__ out, int K, int N)
{
    const int n   = blockIdx.x;
    const int tid = threadIdx.x;

    float acc[BATCH];
#pragma unroll
    for (int b = 0; b < BATCH; b++) acc[b] = 0.f;

    const float4* Wv = (const float4*)(W + (size_t)n * K);
    const int K4 = K >> 2;

    for (int k4 = tid; k4 < K4; k4 += 256) {
        float4 w = __ldg(Wv + k4);
#pragma unroll
        for (int b = 0; b < BATCH; b++) {
            float4 x = __ldg((const float4*)(X + (size_t)b * K) + k4);
            acc[b] += w.x * x.x + w.y * x.y + w.z * x.z + w.w * x.w;
        }
    }

    // intra-warp reduce (lane 0 ends with the warp total per b)
#pragma unroll
    for (int b = 0; b < BATCH; b++) {
#pragma unroll
        for (int off = 16; off; off >>= 1)
            acc[b] += __shfl_xor_sync(0xffffffffu, acc[b], off);
    }

    __shared__ float red[8][BATCH];
    const int warp = tid >> 5;
    const int lane = tid & 31;
    if (lane == 0) {
#pragma unroll
        for (int b = 0; b < BATCH; b++) red[warp][b] = acc[b];
    }
    __syncthreads();

    if (tid < BATCH) {
        float s = 0.f;
#pragma unroll
        for (int w = 0; w < 8; w++) s += red[w][tid];
        out[tid * N + n] = s + __ldg(bias + n);
    }
}

// ---------------------------------------------------------------------------
// Fused broadcast-add + LayerNorm(C).
//   in : spatial [B, C, S]  (S contiguous)
//   proj[B, C] broadcast over S
//   out: y[B, C, S]  LN over C for each (b, s). Spatial read exactly once.
// ---------------------------------------------------------------------------
__global__ void __launch_bounds__(THREADS) fused_add_ln(
    const float* __restrict__ spatial,
    const float* __restrict__ proj,
    const float* __restrict__ gamma,
    const float* __restrict__ beta,
    float* __restrict__ out)
{
    extern __shared__ float smem[];
    float* tile    = smem;                    // CDIM * PIX
    float* proj_s  = tile   + CDIM * PIX;     // CDIM
    float* gamma_s = proj_s + CDIM;           // CDIM
    float* beta_s  = gamma_s + CDIM;          // CDIM
    float* psum    = beta_s + CDIM;           // 8 * PIX
    float* psq     = psum   + 8 * PIX;        // 8 * PIX
    float* mean_s  = psq    + 8 * PIX;        // PIX
    float* rstd_s  = mean_s + PIX;            // PIX

    const int b  = blockIdx.x >> 7;           // / (SDIM/PIX = 128)
    const int s0 = (blockIdx.x & 127) * PIX;
    const int tid = threadIdx.x;

    for (int i = tid; i < CDIM; i += THREADS) {
        proj_s[i]  = proj[b * CDIM + i];
        gamma_s[i] = gamma[i];
        beta_s[i]  = beta[i];
    }
    __syncthreads();

    const size_t gbase = (size_t)b * CDIM * SDIM + s0;
    const int p4 = tid & 7;        // which float4 within the 32-pixel row
    const int c0 = tid >> 3;       // c row, stepped by 32

    // ---- load + broadcast add: one DRAM read of the tile ----
#pragma unroll
    for (int it = 0; it < CDIM / 32; it++) {
        int c = c0 + it * 32;
        float4 v = *(const float4*)(spatial + gbase + (size_t)c * SDIM + p4 * 4);
        float pj = proj_s[c];
        v.x += pj; v.y += pj; v.z += pj; v.w += pj;
        *(float4*)(tile + c * PIX + p4 * 4) = v;
    }
    __syncthreads();

    // ---- stats: 8 threads per pixel, conflict-free (bank = p) ----
    {
        const int p   = tid & 31;
        const int sub = tid >> 5;          // 0..7
        float s = 0.f, sq = 0.f;
        const int cbeg = sub * (CDIM / 8);
#pragma unroll 8
        for (int c = cbeg; c < cbeg + CDIM / 8; c++) {
            float x = tile[c * PIX + p];
            s  += x;
            sq += x * x;
        }
        psum[sub * PIX + p] = s;
        psq [sub * PIX + p] = sq;
    }
    __syncthreads();

    if (tid < PIX) {
        float s = 0.f, sq = 0.f;
#pragma unroll
        for (int i = 0; i < 8; i++) { s += psum[i * PIX + tid]; sq += psq[i * PIX + tid]; }
        const float inv = 1.0f / CDIM;
        float mu  = s * inv;
        float var = sq * inv - mu * mu;
        mean_s[tid] = mu;
        rstd_s[tid] = rsqrtf(var + 1e-5f);
    }
    __syncthreads();

    // ---- normalize + store ----
    const float4 mu4 = *(const float4*)(mean_s + p4 * 4);
    const float4 rs4 = *(const float4*)(rstd_s + p4 * 4);
#pragma unroll
    for (int it = 0; it < CDIM / 32; it++) {
        int c = c0 + it * 32;
        float4 v = *(const float4*)(tile + c * PIX + p4 * 4);
        float g  = gamma_s[c];
        float bt = beta_s[c];
        v.x = (v.x - mu4.x) * rs4.x * g + bt;
        v.y = (v.y - mu4.y) * rs4.y * g + bt;
        v.z = (v.z - mu4.z) * rs4.z * g + bt;
        v.w = (v.w - mu4.w) * rs4.w * g + bt;
        *(float4*)(out + gbase + (size_t)c * SDIM + p4 * 4) = v;
    }
}

// ---------------------------------------------------------------------------
// Launcher
// ---------------------------------------------------------------------------
extern "C" void kernel_launch(void* const* d_in, const int* in_sizes, int n_in,
                              void* d_out, int out_size)
{
    const float* spatial     = (const float*)d_in[0];
    const float* conditioning= (const float*)d_in[1];
    const float* w_cond      = (const float*)d_in[2];
    const float* b_cond      = (const float*)d_in[3];
    const float* in_proj_w   = (const float*)d_in[4];
    const float* in_proj_b   = (const float*)d_in[5];
    const float* attn_out_w  = (const float*)d_in[6];
    const float* attn_out_b  = (const float*)d_in[7];
    const float* w_out       = (const float*)d_in[8];
    const float* b_out       = (const float*)d_in[9];
    const float* ln_gamma    = (const float*)d_in[10];
    const float* ln_beta     = (const float*)d_in[11];
    float* out = (float*)d_out;

    float *tmp0, *tmp1;
    cudaGetSymbolAddress((void**)&tmp0, g_tmp0);
    cudaGetSymbolAddress((void**)&tmp1, g_tmp1);

    const int smem_bytes = (CDIM * PIX + 3 * CDIM + 16 * PIX + 2 * PIX) * sizeof(float);
    cudaFuncSetAttribute(fused_add_ln, cudaFuncAttributeMaxDynamicSharedMemorySize, smem_bytes);

    // cond = conditioning @ w_cond^T + b_cond
    gemm16_col<<<CDIM, 256>>>(conditioning, w_cond, b_cond, tmp0, KCOND, CDIM);
    // v = cond @ wv^T + bv   (wv = in_proj_w rows [2C, 3C))
    gemm16_col<<<CDIM, 256>>>(tmp0, in_proj_w + 2 * CDIM * CDIM, in_proj_b + 2 * CDIM,
                              tmp1, CDIM, CDIM);
    // attn = v @ attn_out_w^T + attn_out_b
    gemm16_col<<<CDIM, 256>>>(tmp1, attn_out_w, attn_out_b, tmp0, CDIM, CDIM);
    // proj = attn @ w_out^T + b_out
    gemm16_col<<<CDIM, 256>>>(tmp0, w_out, b_out, tmp1, CDIM, CDIM);

    // fused add + layernorm
    fused_add_ln<<<BATCH * (SDIM / PIX), THREADS, smem_bytes>>>(
        spatial, tmp1, ln_gamma, ln_beta, out);
}